// round 11
// baseline (speedup 1.0000x reference)
#include <cuda_runtime.h>
#include <math.h>
#include <float.h>
#include <stdint.h>

// Problem constants
#define B_    2
#define T_    2048
#define DM_   2048
#define H_    16
#define HKV_  4
#define DK_   128
#define GRP_  (H_/HKV_)

// Scratch (static device globals; no allocation allowed)
__device__ float g_Q[(size_t)B_*T_*H_*DK_];     // [B,T,H,DK] == [M,2048]
__device__ float g_K[(size_t)B_*T_*HKV_*DK_];   // [M,512]
__device__ float g_V[(size_t)B_*T_*HKV_*DK_];   // [M,512]
__device__ float g_O[(size_t)B_*T_*H_*DK_];
// tf32-pre-rounded copies
__device__ float g_Xc[(size_t)B_*T_*DM_];
__device__ float g_Wqkv[(size_t)(H_*DK_ + 2*HKV_*DK_)*DM_];   // [3072,2048]
__device__ float g_Woc[(size_t)DM_*DM_];

__device__ __forceinline__ unsigned f2tf32(float x) {
    unsigned r;
    asm("cvt.rna.tf32.f32 %0, %1;" : "=r"(r) : "f"(x));
    return r;
}
__device__ __forceinline__ float roundtf(float x) {
    return __uint_as_float(f2tf32(x));
}

__device__ __forceinline__ void mma_tf32(float* c, const unsigned* a, const unsigned* b) {
    asm volatile(
        "mma.sync.aligned.m16n8k8.row.col.f32.tf32.tf32.f32 "
        "{%0,%1,%2,%3}, {%4,%5,%6,%7}, {%8,%9}, {%0,%1,%2,%3};\n"
        : "+f"(c[0]), "+f"(c[1]), "+f"(c[2]), "+f"(c[3])
        : "r"(a[0]), "r"(a[1]), "r"(a[2]), "r"(a[3]), "r"(b[0]), "r"(b[1]));
}

__device__ __forceinline__ void cp16(unsigned dst, const void* src) {
    asm volatile("cp.async.ca.shared.global [%0], [%1], 16;\n" :: "r"(dst), "l"(src));
}
__device__ __forceinline__ void cp_commit() {
    asm volatile("cp.async.commit_group;\n" ::: "memory");
}
template<int N> __device__ __forceinline__ void cp_wait() {
    asm volatile("cp.async.wait_group %0;\n" :: "n"(N) : "memory");
}

// ---------------------------------------------------------------------------
// Pre-round a buffer to tf32 bits (rna). n4 = n/4.
// ---------------------------------------------------------------------------
__global__ void round_tf32_kernel(const float* __restrict__ in,
                                  float* __restrict__ out, int n4)
{
    int i = blockIdx.x * blockDim.x + threadIdx.x;
    if (i < n4) {
        float4 v = ((const float4*)in)[i];
        ((uint4*)out)[i] = make_uint4(f2tf32(v.x), f2tf32(v.y),
                                      f2tf32(v.z), f2tf32(v.w));
    }
}

// ---------------------------------------------------------------------------
// TF32 GEMM v3: 3-stage cp.async, CTA 128x128, 4 warps, warp tile 64x64.
// C[m,n] = sum_k A[m,k]*W[n,k]; inputs pre-rounded to tf32 bits.
// fused=1: ignore C/N/round_out, route output segment to g_Q/g_K/g_V
//          (N=3072 = 2048 Q | 512 K | 512 V; V segment tf32-rounded).
// ---------------------------------------------------------------------------
#define GSTG 3
#define SPAD 20
#define GST_WORDS (128 * SPAD)          // per-matrix stage words

__global__ __launch_bounds__(128) void gemm_tf32(
    const float* __restrict__ A, const float* __restrict__ W,
    float* __restrict__ C, int M, int N, int K, int round_out, int fused)
{
    extern __shared__ unsigned gsm[];
    unsigned* As = gsm;                         // [GSTG][GST_WORDS]
    unsigned* Bs = gsm + GSTG * GST_WORDS;

    const int tid  = threadIdx.x;
    const int lane = tid & 31;
    const int warp = tid >> 5;
    const int wm   = warp >> 1;        // 0..1
    const int wn   = warp & 1;         // 0..1
    const int row0 = blockIdx.y * 128;
    const int col0 = blockIdx.x * 128;

    const float* Ag = A + (size_t)(row0 + tid) * K;   // thread loads row `tid`
    const float* Wg = W + (size_t)(col0 + tid) * K;

    const int g4 = lane >> 2;
    const int q4 = lane & 3;

    const unsigned sA = (unsigned)__cvta_generic_to_shared(As);
    const unsigned sB = (unsigned)__cvta_generic_to_shared(Bs);

    // 4 cp16 per matrix per thread: row `tid`, 16 floats
#define G_ISSUE(s, k0) do {                                                   \
        unsigned da = sA + (unsigned)(((s) * GST_WORDS + tid * SPAD) * 4);    \
        unsigned db = sB + (unsigned)(((s) * GST_WORDS + tid * SPAD) * 4);    \
        _Pragma("unroll")                                                     \
        for (int c_ = 0; c_ < 4; c_++) {                                      \
            cp16(da + c_ * 16, Ag + (k0) + c_ * 4);                           \
            cp16(db + c_ * 16, Wg + (k0) + c_ * 4);                           \
        }                                                                     \
    } while (0)

    float acc[4][8][4];
#pragma unroll
    for (int i = 0; i < 4; i++)
#pragma unroll
        for (int j = 0; j < 8; j++)
#pragma unroll
            for (int r = 0; r < 4; r++) acc[i][j][r] = 0.f;

    G_ISSUE(0, 0);  cp_commit();
    G_ISSUE(1, 16); cp_commit();

    const int niter = K / 16;
    int rd = 0, wr = 2;
    for (int it = 0; it < niter; it++) {
        cp_wait<1>();
        __syncthreads();
        if (it + 2 < niter) G_ISSUE(wr, (it + 2) * 16);
        cp_commit();

        const unsigned* Asr = As + rd * GST_WORDS;
        const unsigned* Bsr = Bs + rd * GST_WORDS;
#pragma unroll
        for (int kk = 0; kk < 2; kk++) {
            const int kb = kk * 8;
            unsigned af[4][4];
#pragma unroll
            for (int ma = 0; ma < 4; ma++) {
                int r = wm * 64 + ma * 16 + g4;
                af[ma][0] = Asr[(r    ) * SPAD + kb + q4];
                af[ma][1] = Asr[(r + 8) * SPAD + kb + q4];
                af[ma][2] = Asr[(r    ) * SPAD + kb + 4 + q4];
                af[ma][3] = Asr[(r + 8) * SPAD + kb + 4 + q4];
            }
            unsigned bf[8][2];
#pragma unroll
            for (int na = 0; na < 8; na++) {
                int c = wn * 64 + na * 8 + g4;
                bf[na][0] = Bsr[c * SPAD + kb + q4];
                bf[na][1] = Bsr[c * SPAD + kb + 4 + q4];
            }
#pragma unroll
            for (int ma = 0; ma < 4; ma++)
#pragma unroll
                for (int na = 0; na < 8; na++)
                    mma_tf32(acc[ma][na], af[ma], bf[na]);
        }
        rd = (rd + 1 == GSTG) ? 0 : rd + 1;
        wr = (wr + 1 == GSTG) ? 0 : wr + 1;
    }

    // epilogue: pick output segment
    float* Cout = C;
    int Nout = N, colbase = col0, ro = round_out;
    if (fused) {
        if (col0 < 2048)      { Cout = g_Q; Nout = 2048; colbase = col0;        ro = 0; }
        else if (col0 < 2560) { Cout = g_K; Nout = 512;  colbase = col0 - 2048; ro = 0; }
        else                  { Cout = g_V; Nout = 512;  colbase = col0 - 2560; ro = 1; }
    }
#pragma unroll
    for (int ma = 0; ma < 4; ma++) {
#pragma unroll
        for (int na = 0; na < 8; na++) {
            int r = row0 + wm * 64 + ma * 16 + g4;
            int c = colbase + wn * 64 + na * 8 + 2 * q4;
            float v0 = acc[ma][na][0], v1 = acc[ma][na][1];
            float v2 = acc[ma][na][2], v3 = acc[ma][na][3];
            if (ro) {
                v0 = roundtf(v0); v1 = roundtf(v1);
                v2 = roundtf(v2); v3 = roundtf(v3);
            }
            *(float2*)(Cout + (size_t)r * Nout + c) = make_float2(v0, v1);
            *(float2*)(Cout + (size_t)(r + 8) * Nout + c) = make_float2(v2, v3);
        }
    }
#undef G_ISSUE
}

// ---------------------------------------------------------------------------
// Fused RMSNorm + RoPE, in place; outputs tf32-rounded bits.
// ---------------------------------------------------------------------------
__global__ void rmsnorm_rope(float* __restrict__ X, const float* __restrict__ w,
                             int nheads)
{
    int gwarp = (blockIdx.x * blockDim.x + threadIdx.x) >> 5;
    int lane  = threadIdx.x & 31;
    int total = B_ * T_ * nheads;
    if (gwarp >= total) return;

    int t = (gwarp / nheads) % T_;
    float* row = X + (size_t)gwarp * DK_;

    float4 v = *(float4*)(row + lane * 4);
    float ss = v.x * v.x + v.y * v.y + v.z * v.z + v.w * v.w;
#pragma unroll
    for (int o = 16; o; o >>= 1) ss += __shfl_xor_sync(0xffffffffu, ss, o);

    float scale = rsqrtf(ss * (1.0f / DK_) + 1.1920929e-7f);

    float4 wv = *(const float4*)(w + lane * 4);
    float x0 = v.x * scale * wv.x;
    float x1 = v.y * scale * wv.y;
    float x2 = v.z * scale * wv.z;
    float x3 = v.w * scale * wv.w;

    int p0 = lane * 2, p1 = lane * 2 + 1;
    float f0 = powf(10000.0f, -(float)p0 / 64.0f);
    float f1 = powf(10000.0f, -(float)p1 / 64.0f);
    float tf = (float)t;
    float s0, c0, s1, c1;
    sincosf(tf * f0, &s0, &c0);
    sincosf(tf * f1, &s1, &c1);

    float4 out;
    out.x = roundtf(x0 * c0 - x1 * s0);
    out.y = roundtf(x1 * c0 + x0 * s0);
    out.z = roundtf(x2 * c1 - x3 * s1);
    out.w = roundtf(x3 * c1 + x2 * s1);
    *(float4*)(row + lane * 4) = out;
}

// ---------------------------------------------------------------------------
// TF32 legacy-mma flash attention (known good, round 7).
// ---------------------------------------------------------------------------
#define FBM 128
#define FBN 64
#define KVS 132
#define PST 68
#define SKV (2 * 64 * KVS)
#define SM_P (2 * SKV)
#define SM_WORDS (SM_P + 8 * 16 * PST)

__global__ __launch_bounds__(256, 1) void flash_attn_tc()
{
    extern __shared__ unsigned smu[];

    const int qtile = (gridDim.x - 1) - blockIdx.x;
    const int h     = blockIdx.y;
    const int b     = blockIdx.z;
    const int hkv   = h / GRP_;

    const int tid  = threadIdx.x;
    const int lane = tid & 31;
    const int warp = tid >> 5;
    const int g4   = lane >> 2;
    const int q4   = lane & 3;

    const int qrow0 = qtile * FBM;
    const int rA    = qrow0 + warp * 16 + g4;
    const int rB    = rA + 8;
    const int wrmax = qrow0 + warp * 16 + 15;

    const unsigned smem_base = (unsigned)__cvta_generic_to_shared(smu);
    unsigned* Ps = smu + SM_P + warp * (16 * PST);

    {
        const float* Qbase = g_Q + (((size_t)(b * T_ + qrow0) * H_ + h) * DK_);
#pragma unroll
        for (int i = 0; i < 16; i++) {
            int c  = tid + 256 * i;
            int r  = c >> 5;
            int cc = c & 31;
            cp16(smem_base + (unsigned)((r * KVS + cc * 4) * 4),
                 Qbase + (size_t)r * (H_ * DK_) + cc * 4);
        }
        cp_commit();
        cp_wait<0>();
        __syncthreads();
    }

    unsigned qf[16][4];
#pragma unroll
    for (int kat = 0; kat < 16; kat++) {
        int kb = kat * 8;
        int r0 = warp * 16 + g4;
        qf[kat][0] = smu[(r0    ) * KVS + kb + q4];
        qf[kat][1] = smu[(r0 + 8) * KVS + kb + q4];
        qf[kat][2] = smu[(r0    ) * KVS + kb + 4 + q4];
        qf[kat][3] = smu[(r0 + 8) * KVS + kb + 4 + q4];
    }
    __syncthreads();

    const size_t kvrow = (size_t)HKV_ * DK_;
    const float* Kb = g_K + (((size_t)b * T_ * HKV_ + hkv) * DK_);
    const float* Vb = g_V + (((size_t)b * T_ * HKV_ + hkv) * DK_);

#define KV_ISSUE(stg, kt) do {                                               \
        int kb0 = (kt) * FBN;                                                \
        unsigned sb = smem_base + (unsigned)((stg) * SKV * 4);               \
        _Pragma("unroll")                                                    \
        for (int i = 0; i < 16; i++) {                                       \
            int c  = tid + 256 * i;                                          \
            int tn = c >> 11;                                                \
            int r  = (c >> 5) & 63;                                          \
            int cc = c & 31;                                                 \
            const float* src = (tn ? Vb : Kb) + (size_t)(kb0 + r) * kvrow + cc * 4; \
            cp16(sb + (unsigned)(((tn * 64 + r) * KVS + cc * 4) * 4), src);  \
        }                                                                    \
    } while (0)

    float oacc[16][4];
#pragma unroll
    for (int i = 0; i < 16; i++)
#pragma unroll
        for (int j = 0; j < 4; j++) oacc[i][j] = 0.f;
    float m0 = -1e30f, m1 = -1e30f, l0 = 0.f, l1 = 0.f;
    const float sc = 0.08838834764831845f;

    const int nchunks = (qtile + 1) * (FBM / FBN);

    KV_ISSUE(0, 0); cp_commit();

    for (int kt = 0; kt < nchunks; kt++) {
        cp_wait<0>();
        __syncthreads();
        if (kt + 1 < nchunks) KV_ISSUE((kt + 1) & 1, kt + 1);
        cp_commit();

        const int kbase = kt * FBN;
        unsigned* Ks = smu + (kt & 1) * SKV;
        unsigned* Vs = Ks + 64 * KVS;

        if (kbase <= wrmax) {
            float sacc[8][4];
#pragma unroll
            for (int n = 0; n < 8; n++)
#pragma unroll
                for (int j = 0; j < 4; j++) sacc[n][j] = 0.f;

#pragma unroll
            for (int kat = 0; kat < 16; kat++) {
                int kb = kat * 8;
#pragma unroll
                for (int nat = 0; nat < 8; nat++) {
                    unsigned bb[2];
                    bb[0] = Ks[(nat * 8 + g4) * KVS + kb + q4];
                    bb[1] = Ks[(nat * 8 + g4) * KVS + kb + 4 + q4];
                    mma_tf32(sacc[nat], qf[kat], bb);
                }
            }

            const bool needmask = (kbase + FBN - 1 > rA);
#pragma unroll
            for (int nat = 0; nat < 8; nat++) {
                int c0 = kbase + nat * 8 + 2 * q4;
                sacc[nat][0] *= sc; sacc[nat][1] *= sc;
                sacc[nat][2] *= sc; sacc[nat][3] *= sc;
                if (needmask) {
                    if (c0     > rA) sacc[nat][0] = -1e30f;
                    if (c0 + 1 > rA) sacc[nat][1] = -1e30f;
                    if (c0     > rB) sacc[nat][2] = -1e30f;
                    if (c0 + 1 > rB) sacc[nat][3] = -1e30f;
                }
            }

            float mA = -1e30f, mB = -1e30f;
#pragma unroll
            for (int nat = 0; nat < 8; nat++) {
                mA = fmaxf(mA, fmaxf(sacc[nat][0], sacc[nat][1]));
                mB = fmaxf(mB, fmaxf(sacc[nat][2], sacc[nat][3]));
            }
            mA = fmaxf(mA, __shfl_xor_sync(0xffffffffu, mA, 1));
            mA = fmaxf(mA, __shfl_xor_sync(0xffffffffu, mA, 2));
            mB = fmaxf(mB, __shfl_xor_sync(0xffffffffu, mB, 1));
            mB = fmaxf(mB, __shfl_xor_sync(0xffffffffu, mB, 2));

            float nm0 = fmaxf(m0, mA), nm1 = fmaxf(m1, mB);
            float corr0 = __expf(m0 - nm0);
            float corr1 = __expf(m1 - nm1);
            float ps0 = 0.f, ps1 = 0.f;
#pragma unroll
            for (int nat = 0; nat < 8; nat++) {
                sacc[nat][0] = __expf(sacc[nat][0] - nm0);
                sacc[nat][1] = __expf(sacc[nat][1] - nm0);
                sacc[nat][2] = __expf(sacc[nat][2] - nm1);
                sacc[nat][3] = __expf(sacc[nat][3] - nm1);
                ps0 += sacc[nat][0] + sacc[nat][1];
                ps1 += sacc[nat][2] + sacc[nat][3];
            }
            ps0 += __shfl_xor_sync(0xffffffffu, ps0, 1);
            ps0 += __shfl_xor_sync(0xffffffffu, ps0, 2);
            ps1 += __shfl_xor_sync(0xffffffffu, ps1, 1);
            ps1 += __shfl_xor_sync(0xffffffffu, ps1, 2);
            l0 = l0 * corr0 + ps0;
            l1 = l1 * corr1 + ps1;
            m0 = nm0; m1 = nm1;

#pragma unroll
            for (int nv = 0; nv < 16; nv++) {
                oacc[nv][0] *= corr0; oacc[nv][1] *= corr0;
                oacc[nv][2] *= corr1; oacc[nv][3] *= corr1;
            }

#pragma unroll
            for (int nat = 0; nat < 8; nat++) {
                int cc = nat * 8 + 2 * q4;
                *(uint2*)(Ps + g4 * PST + cc) =
                    make_uint2(f2tf32(sacc[nat][0]), f2tf32(sacc[nat][1]));
                *(uint2*)(Ps + (g4 + 8) * PST + cc) =
                    make_uint2(f2tf32(sacc[nat][2]), f2tf32(sacc[nat][3]));
            }
            __syncwarp();

#pragma unroll
            for (int kat = 0; kat < 8; kat++) {
                int kb = kat * 8;
                unsigned af[4];
                af[0] = Ps[(g4    ) * PST + kb + q4];
                af[1] = Ps[(g4 + 8) * PST + kb + q4];
                af[2] = Ps[(g4    ) * PST + kb + 4 + q4];
                af[3] = Ps[(g4 + 8) * PST + kb + 4 + q4];
#pragma unroll
                for (int nv = 0; nv < 16; nv++) {
                    unsigned bb[2];
                    bb[0] = Vs[(kb + q4    ) * KVS + nv * 8 + g4];
                    bb[1] = Vs[(kb + q4 + 4) * KVS + nv * 8 + g4];
                    mma_tf32(oacc[nv], af, bb);
                }
            }
            __syncwarp();
        }
    }

    float inv0 = 1.f / l0, inv1 = 1.f / l1;
    float* OA = g_O + (((size_t)(b * T_ + rA) * H_ + h) * DK_);
    float* OB = g_O + (((size_t)(b * T_ + rB) * H_ + h) * DK_);
#pragma unroll
    for (int nv = 0; nv < 16; nv++) {
        int cc = nv * 8 + 2 * q4;
        *(float2*)(OA + cc) = make_float2(roundtf(oacc[nv][0] * inv0),
                                          roundtf(oacc[nv][1] * inv0));
        *(float2*)(OB + cc) = make_float2(roundtf(oacc[nv][2] * inv1),
                                          roundtf(oacc[nv][3] * inv1));
    }
#undef KV_ISSUE
}

// ---------------------------------------------------------------------------
// Launch
// ---------------------------------------------------------------------------
extern "C" void kernel_launch(void* const* d_in, const int* in_sizes, int n_in,
                              void* d_out, int out_size)
{
    const float* x       = (const float*)d_in[0];
    const float* wq      = (const float*)d_in[1];
    const float* wk      = (const float*)d_in[2];
    const float* wv      = (const float*)d_in[3];
    const float* wo      = (const float*)d_in[4];
    const float* q_normw = (const float*)d_in[5];
    const float* k_normw = (const float*)d_in[6];
    float* out = (float*)d_out;

    float *Q, *K, *V, *O, *Xc, *Wqkv, *Woc;
    cudaGetSymbolAddress((void**)&Q, g_Q);
    cudaGetSymbolAddress((void**)&K, g_K);
    cudaGetSymbolAddress((void**)&V, g_V);
    cudaGetSymbolAddress((void**)&O, g_O);
    cudaGetSymbolAddress((void**)&Xc, g_Xc);
    cudaGetSymbolAddress((void**)&Wqkv, g_Wqkv);
    cudaGetSymbolAddress((void**)&Woc, g_Woc);

    const int M = B_ * T_;   // 4096

    // Pre-round inputs to tf32 bits; concat Wq|Wk|Wv into g_Wqkv
    {
        int nx = M * DM_ / 4;
        round_tf32_kernel<<<(nx + 255) / 256, 256>>>(x, Xc, nx);
        int nq = H_ * DK_ * DM_ / 4;          // 2048*2048/4
        int nk = HKV_ * DK_ * DM_ / 4;        // 512*2048/4
        round_tf32_kernel<<<(nq + 255) / 256, 256>>>(wq, Wqkv, nq);
        round_tf32_kernel<<<(nk + 255) / 256, 256>>>(wk, Wqkv + (size_t)2048 * DM_, nk);
        round_tf32_kernel<<<(nk + 255) / 256, 256>>>(wv, Wqkv + (size_t)2560 * DM_, nk);
        round_tf32_kernel<<<(nq + 255) / 256, 256>>>(wo, Woc, nq);
    }

    int gsmem = GSTG * GST_WORDS * 2 * (int)sizeof(unsigned);   // 61440 B
    cudaFuncSetAttribute(gemm_tf32, cudaFuncAttributeMaxDynamicSharedMemorySize, gsmem);

    // Fused QKV projection (one GEMM, N=3072; epilogue routes Q/K/V)
    gemm_tf32<<<dim3(3072 / 128, M / 128), 128, gsmem>>>(
        Xc, Wqkv, nullptr, M, 3072, DM_, 0, 1);

    // RMSNorm + RoPE on Q and K (outputs tf32-rounded)
    {
        int qrows = B_ * T_ * H_;
        int krows = B_ * T_ * HKV_;
        rmsnorm_rope<<<qrows / 4, 128>>>(Q, q_normw, H_);
        rmsnorm_rope<<<krows / 4, 128>>>(K, k_normw, HKV_);
    }

    // Flash attention (legacy tf32 mma, known good)
    {
        int smem = SM_WORDS * (int)sizeof(unsigned);
        cudaFuncSetAttribute(flash_attn_tc, cudaFuncAttributeMaxDynamicSharedMemorySize, smem);
        flash_attn_tc<<<dim3(T_ / FBM, H_, B_), 256, smem>>>();
    }

    // Output projection
    gemm_tf32<<<dim3(DM_ / 128, M / 128), 128, gsmem>>>(
        O, Woc, out, M, DM_, DM_, 0, 0);
}

// round 12
// speedup vs baseline: 2.2476x; 2.2476x over previous
#include <cuda_runtime.h>
#include <cuda_fp16.h>
#include <math.h>
#include <float.h>
#include <stdint.h>

// Problem constants
#define B_    2
#define T_    2048
#define DM_   2048
#define H_    16
#define HKV_  4
#define DK_   128
#define GRP_  (H_/HKV_)

// Scratch (static device globals)
__device__ float  g_Q[(size_t)B_*T_*H_*DK_];      // fp32 QKV-gemm out (pre-norm)
__device__ float  g_K[(size_t)B_*T_*HKV_*DK_];
__device__ __half g_Qh[(size_t)B_*T_*H_*DK_];     // post-norm fp16
__device__ __half g_Kh[(size_t)B_*T_*HKV_*DK_];
__device__ __half g_Vh[(size_t)B_*T_*HKV_*DK_];
__device__ __half g_Oh[(size_t)B_*T_*H_*DK_];
// fp16 copies of inputs
__device__ __half g_Xh[(size_t)B_*T_*DM_];
__device__ __half g_Wqkvh[(size_t)3072*DM_];
__device__ __half g_Woh[(size_t)DM_*DM_];

__device__ __forceinline__ void mma_f16(float* c, const unsigned* a, const unsigned* b) {
    asm volatile(
        "mma.sync.aligned.m16n8k16.row.col.f32.f16.f16.f32 "
        "{%0,%1,%2,%3}, {%4,%5,%6,%7}, {%8,%9}, {%0,%1,%2,%3};\n"
        : "+f"(c[0]), "+f"(c[1]), "+f"(c[2]), "+f"(c[3])
        : "r"(a[0]), "r"(a[1]), "r"(a[2]), "r"(a[3]), "r"(b[0]), "r"(b[1]));
}

__device__ __forceinline__ void cp16(unsigned dst, const void* src) {
    asm volatile("cp.async.ca.shared.global [%0], [%1], 16;\n" :: "r"(dst), "l"(src));
}
__device__ __forceinline__ void cp_commit() {
    asm volatile("cp.async.commit_group;\n" ::: "memory");
}
template<int N> __device__ __forceinline__ void cp_wait() {
    asm volatile("cp.async.wait_group %0;\n" :: "n"(N) : "memory");
}

// ---------------------------------------------------------------------------
// fp32 -> fp16 conversion kernel. n4 = n/4.
// ---------------------------------------------------------------------------
__global__ void to_half_kernel(const float* __restrict__ in,
                               __half* __restrict__ out, int n4)
{
    int i = blockIdx.x * blockDim.x + threadIdx.x;
    if (i < n4) {
        float4 v = ((const float4*)in)[i];
        __half2 h0 = __floats2half2_rn(v.x, v.y);
        __half2 h1 = __floats2half2_rn(v.z, v.w);
        ((uint2*)out)[i] = make_uint2(*(unsigned*)&h0, *(unsigned*)&h1);
    }
}

// ---------------------------------------------------------------------------
// FP16 GEMM (round-7 geometry): 3-stage cp.async, 256 thr, 8 warps, warp 64x32.
// C[m,n] = sum_k A[m,k]*W[n,k], A/W fp16, accumulate fp32.
// fused=1: N=3072 segments -> Q fp32 | K fp32 | V fp16.
// ---------------------------------------------------------------------------
#define GSTG 3
#define SPADW 20                         // words per 32-half row (16 + 4 pad)
#define GST_WORDS (128 * SPADW)

__global__ __launch_bounds__(256) void gemm_f16(
    const __half* __restrict__ A, const __half* __restrict__ W,
    float* __restrict__ C, int M, int N, int K, int fused)
{
    extern __shared__ unsigned gsm[];
    unsigned* As = gsm;
    unsigned* Bs = gsm + GSTG * GST_WORDS;

    const int tid  = threadIdx.x;
    const int lane = tid & 31;
    const int warp = tid >> 5;
    const int wm   = warp >> 2;        // 0..1
    const int wn   = warp & 3;         // 0..3
    const int row0 = blockIdx.y * 128;
    const int col0 = blockIdx.x * 128;
    const int lrow = tid >> 1;
    const int lk   = (tid & 1) * 16;   // half offset within 32-half row chunk
    const __half* Ag = A + (size_t)(row0 + lrow) * K + lk;
    const __half* Wg = W + (size_t)(col0 + lrow) * K + lk;
    const int g4 = lane >> 2;
    const int q4 = lane & 3;

    const unsigned sA = (unsigned)__cvta_generic_to_shared(As);
    const unsigned sB = (unsigned)__cvta_generic_to_shared(Bs);

#define G_ISSUE(s, k0) do {                                                    \
        unsigned da = sA + (unsigned)(((s) * GST_WORDS + lrow * SPADW + (tid & 1) * 8) * 4); \
        unsigned db = sB + (unsigned)(((s) * GST_WORDS + lrow * SPADW + (tid & 1) * 8) * 4); \
        cp16(da,      Ag + (k0));                                              \
        cp16(da + 16, Ag + (k0) + 8);                                          \
        cp16(db,      Wg + (k0));                                              \
        cp16(db + 16, Wg + (k0) + 8);                                          \
    } while (0)

    float acc[4][4][4];
#pragma unroll
    for (int i = 0; i < 4; i++)
#pragma unroll
        for (int j = 0; j < 4; j++)
#pragma unroll
            for (int r = 0; r < 4; r++) acc[i][j][r] = 0.f;

    G_ISSUE(0, 0);  cp_commit();
    G_ISSUE(1, 32); cp_commit();

    const int niter = K / 32;
    int rd = 0, wr = 2;
    for (int it = 0; it < niter; it++) {
        cp_wait<1>();
        __syncthreads();
        if (it + 2 < niter) G_ISSUE(wr, (it + 2) * 32);
        cp_commit();

        const unsigned* Asr = As + rd * GST_WORDS;
        const unsigned* Bsr = Bs + rd * GST_WORDS;
#pragma unroll
        for (int kk = 0; kk < 2; kk++) {
            const int kb = kk * 8;     // word offset: 8 words = 16 halves = k16
            unsigned af[4][4];
#pragma unroll
            for (int ma = 0; ma < 4; ma++) {
                int r = wm * 64 + ma * 16 + g4;
                af[ma][0] = Asr[(r    ) * SPADW + kb + q4];
                af[ma][1] = Asr[(r + 8) * SPADW + kb + q4];
                af[ma][2] = Asr[(r    ) * SPADW + kb + 4 + q4];
                af[ma][3] = Asr[(r + 8) * SPADW + kb + 4 + q4];
            }
            unsigned bf[4][2];
#pragma unroll
            for (int na = 0; na < 4; na++) {
                int c = wn * 32 + na * 8 + g4;
                bf[na][0] = Bsr[c * SPADW + kb + q4];
                bf[na][1] = Bsr[c * SPADW + kb + 4 + q4];
            }
#pragma unroll
            for (int ma = 0; ma < 4; ma++)
#pragma unroll
                for (int na = 0; na < 4; na++)
                    mma_f16(acc[ma][na], af[ma], bf[na]);
        }
        rd = (rd + 1 == GSTG) ? 0 : rd + 1;
        wr = (wr + 1 == GSTG) ? 0 : wr + 1;
    }

    // epilogue
    int seg = 0;               // 0: plain fp32 C; 1: Q fp32; 2: K fp32; 3: V fp16
    float* Cf = C; int Nout = N; int colbase = col0;
    if (fused) {
        if (col0 < 2048)      { seg = 1; Cf = g_Q; Nout = 2048; colbase = col0; }
        else if (col0 < 2560) { seg = 2; Cf = g_K; Nout = 512;  colbase = col0 - 2048; }
        else                  { seg = 3;          Nout = 512;  colbase = col0 - 2560; }
    }
#pragma unroll
    for (int ma = 0; ma < 4; ma++) {
#pragma unroll
        for (int na = 0; na < 4; na++) {
            int r = row0 + wm * 64 + ma * 16 + g4;
            int c = colbase + wn * 32 + na * 8 + 2 * q4;
            if (seg == 3) {
                __half2 h0 = __floats2half2_rn(acc[ma][na][0], acc[ma][na][1]);
                __half2 h1 = __floats2half2_rn(acc[ma][na][2], acc[ma][na][3]);
                *(__half2*)(g_Vh + (size_t)r * Nout + c) = h0;
                *(__half2*)(g_Vh + (size_t)(r + 8) * Nout + c) = h1;
            } else {
                *(float2*)(Cf + (size_t)r * Nout + c) =
                    make_float2(acc[ma][na][0], acc[ma][na][1]);
                *(float2*)(Cf + (size_t)(r + 8) * Nout + c) =
                    make_float2(acc[ma][na][2], acc[ma][na][3]);
            }
        }
    }
#undef G_ISSUE
}

// ---------------------------------------------------------------------------
// Fused RMSNorm + RoPE: reads fp32, writes fp16.
// ---------------------------------------------------------------------------
__global__ void rmsnorm_rope(const float* __restrict__ X, __half* __restrict__ Xh,
                             const float* __restrict__ w, int nheads)
{
    int gwarp = (blockIdx.x * blockDim.x + threadIdx.x) >> 5;
    int lane  = threadIdx.x & 31;
    int total = B_ * T_ * nheads;
    if (gwarp >= total) return;

    int t = (gwarp / nheads) % T_;
    const float* row = X + (size_t)gwarp * DK_;

    float4 v = *(const float4*)(row + lane * 4);
    float ss = v.x * v.x + v.y * v.y + v.z * v.z + v.w * v.w;
#pragma unroll
    for (int o = 16; o; o >>= 1) ss += __shfl_xor_sync(0xffffffffu, ss, o);

    float scale = rsqrtf(ss * (1.0f / DK_) + 1.1920929e-7f);

    float4 wv = *(const float4*)(w + lane * 4);
    float x0 = v.x * scale * wv.x;
    float x1 = v.y * scale * wv.y;
    float x2 = v.z * scale * wv.z;
    float x3 = v.w * scale * wv.w;

    int p0 = lane * 2, p1 = lane * 2 + 1;
    float f0 = powf(10000.0f, -(float)p0 / 64.0f);
    float f1 = powf(10000.0f, -(float)p1 / 64.0f);
    float tf = (float)t;
    float s0, c0, s1, c1;
    sincosf(tf * f0, &s0, &c0);
    sincosf(tf * f1, &s1, &c1);

    __half2 h0 = __floats2half2_rn(x0 * c0 - x1 * s0, x1 * c0 + x0 * s0);
    __half2 h1 = __floats2half2_rn(x2 * c1 - x3 * s1, x3 * c1 + x2 * s1);
    *(uint2*)(Xh + (size_t)gwarp * DK_ + lane * 4) =
        make_uint2(*(unsigned*)&h0, *(unsigned*)&h1);
}

// ---------------------------------------------------------------------------
// FP16 flash attention, causal, GQA. Structure = round-7 (known good),
// fp16 tiles: KVSH=68 words/row, V B-frags via ldmatrix.x2.trans.
// ---------------------------------------------------------------------------
#define FBM 128
#define FBN 64
#define KVSH 68                       // words per 128-half row (64 + 4 pad)
#define SKVH (2 * 64 * KVSH)          // one K+V stage (words) = 8704
#define SMPH (2 * SKVH)               // P region offset = 17408
#define PSTH 36                       // words per 64-half P row (32 + 4 pad)
#define SMW_H (SMPH + 8 * 16 * PSTH)  // 22016 words = 88064 B

__global__ __launch_bounds__(256) void flash_attn_f16()
{
    extern __shared__ unsigned smu[];

    const int qtile = (gridDim.x - 1) - blockIdx.x;   // heavy tiles first
    const int h     = blockIdx.y;
    const int b     = blockIdx.z;
    const int hkv   = h / GRP_;

    const int tid  = threadIdx.x;
    const int lane = tid & 31;
    const int warp = tid >> 5;
    const int g4   = lane >> 2;
    const int q4   = lane & 3;

    const int qrow0 = qtile * FBM;
    const int rA    = qrow0 + warp * 16 + g4;
    const int rB    = rA + 8;
    const int wrmax = qrow0 + warp * 16 + 15;

    const unsigned smem_base = (unsigned)__cvta_generic_to_shared(smu);
    unsigned* Ps = smu + SMPH + warp * (16 * PSTH);

    // ---- prologue: cp.async Q tile (128 rows x 128 halves = 2048 x 16B) ----
    {
        const __half* Qbase = g_Qh + (((size_t)(b * T_ + qrow0) * H_ + h) * DK_);
#pragma unroll
        for (int i = 0; i < 8; i++) {
            int c  = tid + 256 * i;          // 0..2047
            int r  = c >> 4;                 // 0..127
            int cc = c & 15;                 // 16B chunk (8 halves)
            cp16(smem_base + (unsigned)((r * KVSH + cc * 4) * 4),
                 Qbase + (size_t)r * (H_ * DK_) + cc * 8);
        }
        cp_commit();
        cp_wait<0>();
        __syncthreads();
    }

    unsigned qf[8][4];
#pragma unroll
    for (int kat = 0; kat < 8; kat++) {
        int kb = kat * 8;                    // word offset = k16 step
        int r0 = warp * 16 + g4;
        qf[kat][0] = smu[(r0    ) * KVSH + kb + q4];
        qf[kat][1] = smu[(r0 + 8) * KVSH + kb + q4];
        qf[kat][2] = smu[(r0    ) * KVSH + kb + 4 + q4];
        qf[kat][3] = smu[(r0 + 8) * KVSH + kb + 4 + q4];
    }
    __syncthreads();

    const size_t kvrow = (size_t)HKV_ * DK_;
    const __half* Kb = g_Kh + (((size_t)b * T_ * HKV_ + hkv) * DK_);
    const __half* Vb = g_Vh + (((size_t)b * T_ * HKV_ + hkv) * DK_);

#define KV_ISSUE(stg, kt) do {                                                \
        int kb0 = (kt) * FBN;                                                 \
        unsigned sb = smem_base + (unsigned)((stg) * SKVH * 4);               \
        _Pragma("unroll")                                                     \
        for (int i = 0; i < 8; i++) {                                         \
            int c  = tid + 256 * i;        /* 0..2047 */                      \
            int tn = c >> 10;              /* 0=K, 1=V */                     \
            int r  = (c >> 4) & 63;                                           \
            int cc = c & 15;                                                  \
            const __half* src = (tn ? Vb : Kb) + (size_t)(kb0 + r) * kvrow + cc * 8; \
            cp16(sb + (unsigned)(((tn * 64 + r) * KVSH + cc * 4) * 4), src);  \
        }                                                                     \
    } while (0)

    float oacc[16][4];
#pragma unroll
    for (int i = 0; i < 16; i++)
#pragma unroll
        for (int j = 0; j < 4; j++) oacc[i][j] = 0.f;
    float m0 = -1e30f, m1 = -1e30f, l0 = 0.f, l1 = 0.f;
    const float sc = 0.08838834764831845f;

    const int nchunks = (qtile + 1) * (FBM / FBN);

    KV_ISSUE(0, 0); cp_commit();

    for (int kt = 0; kt < nchunks; kt++) {
        cp_wait<0>();
        __syncthreads();
        if (kt + 1 < nchunks) KV_ISSUE((kt + 1) & 1, kt + 1);
        cp_commit();

        const int kbase = kt * FBN;
        unsigned* Ks = smu + (kt & 1) * SKVH;
        const unsigned vbase = smem_base +
            (unsigned)(((kt & 1) * SKVH + 64 * KVSH) * 4);

        if (kbase <= wrmax) {
            // ---- S = Q K^T  (8 k16-steps x 8 key-tiles) ----
            float sacc[8][4];
#pragma unroll
            for (int n = 0; n < 8; n++)
#pragma unroll
                for (int j = 0; j < 4; j++) sacc[n][j] = 0.f;

#pragma unroll
            for (int kat = 0; kat < 8; kat++) {
                int kb = kat * 8;
#pragma unroll
                for (int nat = 0; nat < 8; nat++) {
                    unsigned bb[2];
                    bb[0] = Ks[(nat * 8 + g4) * KVSH + kb + q4];
                    bb[1] = Ks[(nat * 8 + g4) * KVSH + kb + 4 + q4];
                    mma_f16(sacc[nat], qf[kat], bb);
                }
            }

            // ---- scale + causal mask ----
            const bool needmask = (kbase + FBN - 1 > rA);
#pragma unroll
            for (int nat = 0; nat < 8; nat++) {
                int c0 = kbase + nat * 8 + 2 * q4;
                sacc[nat][0] *= sc; sacc[nat][1] *= sc;
                sacc[nat][2] *= sc; sacc[nat][3] *= sc;
                if (needmask) {
                    if (c0     > rA) sacc[nat][0] = -1e30f;
                    if (c0 + 1 > rA) sacc[nat][1] = -1e30f;
                    if (c0     > rB) sacc[nat][2] = -1e30f;
                    if (c0 + 1 > rB) sacc[nat][3] = -1e30f;
                }
            }

            // ---- online softmax (warp-local) ----
            float mA = -1e30f, mB = -1e30f;
#pragma unroll
            for (int nat = 0; nat < 8; nat++) {
                mA = fmaxf(mA, fmaxf(sacc[nat][0], sacc[nat][1]));
                mB = fmaxf(mB, fmaxf(sacc[nat][2], sacc[nat][3]));
            }
            mA = fmaxf(mA, __shfl_xor_sync(0xffffffffu, mA, 1));
            mA = fmaxf(mA, __shfl_xor_sync(0xffffffffu, mA, 2));
            mB = fmaxf(mB, __shfl_xor_sync(0xffffffffu, mB, 1));
            mB = fmaxf(mB, __shfl_xor_sync(0xffffffffu, mB, 2));

            float nm0 = fmaxf(m0, mA), nm1 = fmaxf(m1, mB);
            float corr0 = __expf(m0 - nm0);
            float corr1 = __expf(m1 - nm1);
            float ps0 = 0.f, ps1 = 0.f;
#pragma unroll
            for (int nat = 0; nat < 8; nat++) {
                sacc[nat][0] = __expf(sacc[nat][0] - nm0);
                sacc[nat][1] = __expf(sacc[nat][1] - nm0);
                sacc[nat][2] = __expf(sacc[nat][2] - nm1);
                sacc[nat][3] = __expf(sacc[nat][3] - nm1);
                ps0 += sacc[nat][0] + sacc[nat][1];
                ps1 += sacc[nat][2] + sacc[nat][3];
            }
            ps0 += __shfl_xor_sync(0xffffffffu, ps0, 1);
            ps0 += __shfl_xor_sync(0xffffffffu, ps0, 2);
            ps1 += __shfl_xor_sync(0xffffffffu, ps1, 1);
            ps1 += __shfl_xor_sync(0xffffffffu, ps1, 2);
            l0 = l0 * corr0 + ps0;
            l1 = l1 * corr1 + ps1;
            m0 = nm0; m1 = nm1;

#pragma unroll
            for (int nv = 0; nv < 16; nv++) {
                oacc[nv][0] *= corr0; oacc[nv][1] *= corr0;
                oacc[nv][2] *= corr1; oacc[nv][3] *= corr1;
            }

            // ---- stash P (fp16) into per-warp smem tile ----
#pragma unroll
            for (int nat = 0; nat < 8; nat++) {
                int wc = nat * 4 + q4;     // word = (nat*8 + 2q4)/2
                __half2 h0 = __floats2half2_rn(sacc[nat][0], sacc[nat][1]);
                __half2 h1 = __floats2half2_rn(sacc[nat][2], sacc[nat][3]);
                Ps[g4 * PSTH + wc]       = *(unsigned*)&h0;
                Ps[(g4 + 8) * PSTH + wc] = *(unsigned*)&h1;
            }
            __syncwarp();

            // ---- O += P V   (4 k16-steps x 16 dk-tiles) ----
#pragma unroll
            for (int kat = 0; kat < 4; kat++) {
                int kb = kat * 8;          // word offset into P row (k16)
                unsigned af[4];
                af[0] = Ps[(g4    ) * PSTH + kb + q4];
                af[1] = Ps[(g4 + 8) * PSTH + kb + q4];
                af[2] = Ps[(g4    ) * PSTH + kb + 4 + q4];
                af[3] = Ps[(g4 + 8) * PSTH + kb + 4 + q4];
                unsigned vrow = vbase +
                    (unsigned)(((kat * 16 + (lane & 15)) * KVSH) * 4);
#pragma unroll
                for (int nv = 0; nv < 16; nv++) {
                    unsigned bb[2];
                    asm volatile(
                        "ldmatrix.sync.aligned.m8n8.x2.trans.shared.b16 {%0,%1}, [%2];"
                        : "=r"(bb[0]), "=r"(bb[1])
                        : "r"(vrow + (unsigned)(nv * 16)));
                    mma_f16(oacc[nv], af, bb);
                }
            }
            __syncwarp();
        }
    }

    // ---- epilogue (fp16 O feeds O-proj GEMM) ----
    float inv0 = 1.f / l0, inv1 = 1.f / l1;
    __half* OA = g_Oh + (((size_t)(b * T_ + rA) * H_ + h) * DK_);
    __half* OB = g_Oh + (((size_t)(b * T_ + rB) * H_ + h) * DK_);
#pragma unroll
    for (int nv = 0; nv < 16; nv++) {
        int cc = nv * 8 + 2 * q4;
        *(__half2*)(OA + cc) = __floats2half2_rn(oacc[nv][0] * inv0, oacc[nv][1] * inv0);
        *(__half2*)(OB + cc) = __floats2half2_rn(oacc[nv][2] * inv1, oacc[nv][3] * inv1);
    }
#undef KV_ISSUE
}

// ---------------------------------------------------------------------------
// Launch
// ---------------------------------------------------------------------------
extern "C" void kernel_launch(void* const* d_in, const int* in_sizes, int n_in,
                              void* d_out, int out_size)
{
    const float* x       = (const float*)d_in[0];
    const float* wq      = (const float*)d_in[1];
    const float* wk      = (const float*)d_in[2];
    const float* wv      = (const float*)d_in[3];
    const float* wo      = (const float*)d_in[4];
    const float* q_normw = (const float*)d_in[5];
    const float* k_normw = (const float*)d_in[6];
    float* out = (float*)d_out;

    float *Q, *K;
    __half *Qh, *Kh, *Xh, *Wqkvh, *Woh, *Oh;
    cudaGetSymbolAddress((void**)&Q, g_Q);
    cudaGetSymbolAddress((void**)&K, g_K);
    cudaGetSymbolAddress((void**)&Qh, g_Qh);
    cudaGetSymbolAddress((void**)&Kh, g_Kh);
    cudaGetSymbolAddress((void**)&Xh, g_Xh);
    cudaGetSymbolAddress((void**)&Wqkvh, g_Wqkvh);
    cudaGetSymbolAddress((void**)&Woh, g_Woh);
    cudaGetSymbolAddress((void**)&Oh, g_Oh);

    const int M = B_ * T_;   // 4096

    // Convert inputs to fp16; concat Wq|Wk|Wv
    {
        int nx = M * DM_ / 4;
        to_half_kernel<<<(nx + 255) / 256, 256>>>(x, Xh, nx);
        int nq = H_ * DK_ * DM_ / 4;
        int nk = HKV_ * DK_ * DM_ / 4;
        to_half_kernel<<<(nq + 255) / 256, 256>>>(wq, Wqkvh, nq);
        to_half_kernel<<<(nk + 255) / 256, 256>>>(wk, Wqkvh + (size_t)2048 * DM_, nk);
        to_half_kernel<<<(nk + 255) / 256, 256>>>(wv, Wqkvh + (size_t)2560 * DM_, nk);
        to_half_kernel<<<(nq + 255) / 256, 256>>>(wo, Woh, nq);
    }

    int gsmem = GSTG * GST_WORDS * 2 * (int)sizeof(unsigned);   // 61440 B
    cudaFuncSetAttribute(gemm_f16, cudaFuncAttributeMaxDynamicSharedMemorySize, gsmem);

    // Fused QKV projection
    gemm_f16<<<dim3(3072 / 128, M / 128), 256, gsmem>>>(
        Xh, Wqkvh, nullptr, M, 3072, DM_, 1);

    // RMSNorm + RoPE (fp32 in, fp16 out)
    {
        int qrows = B_ * T_ * H_;
        int krows = B_ * T_ * HKV_;
        rmsnorm_rope<<<qrows / 4, 128>>>(Q, Qh, q_normw, H_);
        rmsnorm_rope<<<krows / 4, 128>>>(K, Kh, k_normw, HKV_);
    }

    // FP16 flash attention
    {
        int smem = SMW_H * (int)sizeof(unsigned);   // 88064 B
        cudaFuncSetAttribute(flash_attn_f16, cudaFuncAttributeMaxDynamicSharedMemorySize, smem);
        flash_attn_f16<<<dim3(T_ / FBM, H_, B_), 256, smem>>>();
    }

    // Output projection (fp16 in, fp32 out)
    gemm_f16<<<dim3(DM_ / 128, M / 128), 256, gsmem>>>(
        Oh, Woh, out, M, DM_, DM_, 0);
}

// round 15
// speedup vs baseline: 2.2851x; 1.0167x over previous
#include <cuda_runtime.h>
#include <cuda_fp16.h>
#include <math.h>
#include <float.h>
#include <stdint.h>

// Problem constants
#define B_    2
#define T_    2048
#define DM_   2048
#define H_    16
#define HKV_  4
#define DK_   128
#define GRP_  (H_/HKV_)

// Scratch (static device globals)
__device__ float  g_Q[(size_t)B_*T_*H_*DK_];      // fp32 QKV-gemm out (pre-norm)
__device__ float  g_K[(size_t)B_*T_*HKV_*DK_];
__device__ __half g_Qh[(size_t)B_*T_*H_*DK_];     // post-norm fp16
__device__ __half g_Kh[(size_t)B_*T_*HKV_*DK_];
__device__ __half g_Vh[(size_t)B_*T_*HKV_*DK_];
__device__ __half g_Oh[(size_t)B_*T_*H_*DK_];
// fp16 copies of inputs
__device__ __half g_Xh[(size_t)B_*T_*DM_];
__device__ __half g_Wqkvh[(size_t)3072*DM_];
__device__ __half g_Woh[(size_t)DM_*DM_];

__device__ __forceinline__ void mma_f16(float* c, const unsigned* a, const unsigned* b) {
    asm volatile(
        "mma.sync.aligned.m16n8k16.row.col.f32.f16.f16.f32 "
        "{%0,%1,%2,%3}, {%4,%5,%6,%7}, {%8,%9}, {%0,%1,%2,%3};\n"
        : "+f"(c[0]), "+f"(c[1]), "+f"(c[2]), "+f"(c[3])
        : "r"(a[0]), "r"(a[1]), "r"(a[2]), "r"(a[3]), "r"(b[0]), "r"(b[1]));
}

__device__ __forceinline__ void cp16(unsigned dst, const void* src) {
    asm volatile("cp.async.ca.shared.global [%0], [%1], 16;\n" :: "r"(dst), "l"(src));
}
__device__ __forceinline__ void cp_commit() {
    asm volatile("cp.async.commit_group;\n" ::: "memory");
}
template<int N> __device__ __forceinline__ void cp_wait() {
    asm volatile("cp.async.wait_group %0;\n" :: "n"(N) : "memory");
}

// ---------------------------------------------------------------------------
// One fused fp32->fp16 conversion for all five inputs (routed by index).
// Segments (float4 units): x | wq | wk | wv | wo.
// ---------------------------------------------------------------------------
#define CNX (B_*T_*DM_/4)          // 2097152
#define CNQ (2048*2048/4)          // 1048576
#define CNK (512*2048/4)           //  262144
#define CN_TOTAL (CNX + CNQ + CNK + CNK + CNQ)   // 4718592

__global__ void convert_all_kernel(const float* __restrict__ x,
                                   const float* __restrict__ wq,
                                   const float* __restrict__ wk,
                                   const float* __restrict__ wv,
                                   const float* __restrict__ wo)
{
    int i = blockIdx.x * blockDim.x + threadIdx.x;
    if (i >= CN_TOTAL) return;

    const float* src;
    __half* dst;
    int off = i;
    if (off < CNX)                 { src = x;  dst = g_Xh; }
    else if ((off -= CNX) < CNQ)   { src = wq; dst = g_Wqkvh; }
    else if ((off -= CNQ) < CNK)   { src = wk; dst = g_Wqkvh + (size_t)2048 * DM_; }
    else if ((off -= CNK) < CNK)   { src = wv; dst = g_Wqkvh + (size_t)2560 * DM_; }
    else                           { off -= CNK; src = wo; dst = g_Woh; }

    float4 v = ((const float4*)src)[off];
    __half2 h0 = __floats2half2_rn(v.x, v.y);
    __half2 h1 = __floats2half2_rn(v.z, v.w);
    ((uint2*)dst)[off] = make_uint2(*(unsigned*)&h0, *(unsigned*)&h1);
}

// ---------------------------------------------------------------------------
// FP16 GEMM (round-12, known good): 3-stage cp.async, 256 thr, warp 64x32.
// fused=1: N=3072 segments -> Q fp32 | K fp32 | V fp16.
// ---------------------------------------------------------------------------
#define GSTG 3
#define SPADW 20
#define GST_WORDS (128 * SPADW)

__global__ __launch_bounds__(256) void gemm_f16(
    const __half* __restrict__ A, const __half* __restrict__ W,
    float* __restrict__ C, int M, int N, int K, int fused)
{
    extern __shared__ unsigned gsm[];
    unsigned* As = gsm;
    unsigned* Bs = gsm + GSTG * GST_WORDS;

    const int tid  = threadIdx.x;
    const int lane = tid & 31;
    const int warp = tid >> 5;
    const int wm   = warp >> 2;
    const int wn   = warp & 3;
    const int row0 = blockIdx.y * 128;
    const int col0 = blockIdx.x * 128;
    const int lrow = tid >> 1;
    const int lk   = (tid & 1) * 16;
    const __half* Ag = A + (size_t)(row0 + lrow) * K + lk;
    const __half* Wg = W + (size_t)(col0 + lrow) * K + lk;
    const int g4 = lane >> 2;
    const int q4 = lane & 3;

    const unsigned sA = (unsigned)__cvta_generic_to_shared(As);
    const unsigned sB = (unsigned)__cvta_generic_to_shared(Bs);

#define G_ISSUE(s, k0) do {                                                    \
        unsigned da = sA + (unsigned)(((s) * GST_WORDS + lrow * SPADW + (tid & 1) * 8) * 4); \
        unsigned db = sB + (unsigned)(((s) * GST_WORDS + lrow * SPADW + (tid & 1) * 8) * 4); \
        cp16(da,      Ag + (k0));                                              \
        cp16(da + 16, Ag + (k0) + 8);                                          \
        cp16(db,      Wg + (k0));                                              \
        cp16(db + 16, Wg + (k0) + 8);                                          \
    } while (0)

    float acc[4][4][4];
#pragma unroll
    for (int i = 0; i < 4; i++)
#pragma unroll
        for (int j = 0; j < 4; j++)
#pragma unroll
            for (int r = 0; r < 4; r++) acc[i][j][r] = 0.f;

    G_ISSUE(0, 0);  cp_commit();
    G_ISSUE(1, 32); cp_commit();

    const int niter = K / 32;
    int rd = 0, wr = 2;
    for (int it = 0; it < niter; it++) {
        cp_wait<1>();
        __syncthreads();
        if (it + 2 < niter) G_ISSUE(wr, (it + 2) * 32);
        cp_commit();

        const unsigned* Asr = As + rd * GST_WORDS;
        const unsigned* Bsr = Bs + rd * GST_WORDS;
#pragma unroll
        for (int kk = 0; kk < 2; kk++) {
            const int kb = kk * 8;
            unsigned af[4][4];
#pragma unroll
            for (int ma = 0; ma < 4; ma++) {
                int r = wm * 64 + ma * 16 + g4;
                af[ma][0] = Asr[(r    ) * SPADW + kb + q4];
                af[ma][1] = Asr[(r + 8) * SPADW + kb + q4];
                af[ma][2] = Asr[(r    ) * SPADW + kb + 4 + q4];
                af[ma][3] = Asr[(r + 8) * SPADW + kb + 4 + q4];
            }
            unsigned bf[4][2];
#pragma unroll
            for (int na = 0; na < 4; na++) {
                int c = wn * 32 + na * 8 + g4;
                bf[na][0] = Bsr[c * SPADW + kb + q4];
                bf[na][1] = Bsr[c * SPADW + kb + 4 + q4];
            }
#pragma unroll
            for (int ma = 0; ma < 4; ma++)
#pragma unroll
                for (int na = 0; na < 4; na++)
                    mma_f16(acc[ma][na], af[ma], bf[na]);
        }
        rd = (rd + 1 == GSTG) ? 0 : rd + 1;
        wr = (wr + 1 == GSTG) ? 0 : wr + 1;
    }

    // epilogue
    int seg = 0;               // 0: plain fp32 C; 1: Q fp32; 2: K fp32; 3: V fp16
    float* Cf = C; int Nout = N; int colbase = col0;
    if (fused) {
        if (col0 < 2048)      { seg = 1; Cf = g_Q; Nout = 2048; colbase = col0; }
        else if (col0 < 2560) { seg = 2; Cf = g_K; Nout = 512;  colbase = col0 - 2048; }
        else                  { seg = 3;          Nout = 512;  colbase = col0 - 2560; }
    }
#pragma unroll
    for (int ma = 0; ma < 4; ma++) {
#pragma unroll
        for (int na = 0; na < 4; na++) {
            int r = row0 + wm * 64 + ma * 16 + g4;
            int c = colbase + wn * 32 + na * 8 + 2 * q4;
            if (seg == 3) {
                __half2 h0 = __floats2half2_rn(acc[ma][na][0], acc[ma][na][1]);
                __half2 h1 = __floats2half2_rn(acc[ma][na][2], acc[ma][na][3]);
                *(__half2*)(g_Vh + (size_t)r * Nout + c) = h0;
                *(__half2*)(g_Vh + (size_t)(r + 8) * Nout + c) = h1;
            } else {
                *(float2*)(Cf + (size_t)r * Nout + c) =
                    make_float2(acc[ma][na][0], acc[ma][na][1]);
                *(float2*)(Cf + (size_t)(r + 8) * Nout + c) =
                    make_float2(acc[ma][na][2], acc[ma][na][3]);
            }
        }
    }
#undef G_ISSUE
}

// ---------------------------------------------------------------------------
// Fused RMSNorm + RoPE, single launch covering Q rows then K rows.
// Per-row math identical to the round-12 passer.
// ---------------------------------------------------------------------------
__global__ void rmsnorm_rope_all(const float* __restrict__ qw,
                                 const float* __restrict__ kw)
{
    int gwarp = (blockIdx.x * blockDim.x + threadIdx.x) >> 5;
    int lane  = threadIdx.x & 31;
    const int qrows = B_ * T_ * H_;
    const int krows = B_ * T_ * HKV_;
    if (gwarp >= qrows + krows) return;

    const float* row;
    __half* orow;
    const float* w;
    int t;
    if (gwarp < qrows) {
        row  = g_Q  + (size_t)gwarp * DK_;
        orow = g_Qh + (size_t)gwarp * DK_;
        w = qw;
        t = (gwarp / H_) % T_;
    } else {
        int idx = gwarp - qrows;
        row  = g_K  + (size_t)idx * DK_;
        orow = g_Kh + (size_t)idx * DK_;
        w = kw;
        t = (idx / HKV_) % T_;
    }

    float4 v = *(const float4*)(row + lane * 4);
    float ss = v.x * v.x + v.y * v.y + v.z * v.z + v.w * v.w;
#pragma unroll
    for (int o = 16; o; o >>= 1) ss += __shfl_xor_sync(0xffffffffu, ss, o);

    float scale = rsqrtf(ss * (1.0f / DK_) + 1.1920929e-7f);

    float4 wv = *(const float4*)(w + lane * 4);
    float x0 = v.x * scale * wv.x;
    float x1 = v.y * scale * wv.y;
    float x2 = v.z * scale * wv.z;
    float x3 = v.w * scale * wv.w;

    int p0 = lane * 2, p1 = lane * 2 + 1;
    float f0 = powf(10000.0f, -(float)p0 / 64.0f);
    float f1 = powf(10000.0f, -(float)p1 / 64.0f);
    float tf = (float)t;
    float s0, c0, s1, c1;
    sincosf(tf * f0, &s0, &c0);
    sincosf(tf * f1, &s1, &c1);

    __half2 h0 = __floats2half2_rn(x0 * c0 - x1 * s0, x1 * c0 + x0 * s0);
    __half2 h1 = __floats2half2_rn(x2 * c1 - x3 * s1, x3 * c1 + x2 * s1);
    *(uint2*)(orow + lane * 4) = make_uint2(*(unsigned*)&h0, *(unsigned*)&h1);
}

// ---------------------------------------------------------------------------
// FP16 flash attention, causal, GQA (round-12, known good).
// ---------------------------------------------------------------------------
#define FBM 128
#define FBN 64
#define KVSH 68
#define SKVH (2 * 64 * KVSH)
#define SMPH (2 * SKVH)
#define PSTH 36
#define SMW_H (SMPH + 8 * 16 * PSTH)

__global__ __launch_bounds__(256) void flash_attn_f16()
{
    extern __shared__ unsigned smu[];

    const int qtile = (gridDim.x - 1) - blockIdx.x;
    const int h     = blockIdx.y;
    const int b     = blockIdx.z;
    const int hkv   = h / GRP_;

    const int tid  = threadIdx.x;
    const int lane = tid & 31;
    const int warp = tid >> 5;
    const int g4   = lane >> 2;
    const int q4   = lane & 3;

    const int qrow0 = qtile * FBM;
    const int rA    = qrow0 + warp * 16 + g4;
    const int rB    = rA + 8;
    const int wrmax = qrow0 + warp * 16 + 15;

    const unsigned smem_base = (unsigned)__cvta_generic_to_shared(smu);
    unsigned* Ps = smu + SMPH + warp * (16 * PSTH);

    {
        const __half* Qbase = g_Qh + (((size_t)(b * T_ + qrow0) * H_ + h) * DK_);
#pragma unroll
        for (int i = 0; i < 8; i++) {
            int c  = tid + 256 * i;
            int r  = c >> 4;
            int cc = c & 15;
            cp16(smem_base + (unsigned)((r * KVSH + cc * 4) * 4),
                 Qbase + (size_t)r * (H_ * DK_) + cc * 8);
        }
        cp_commit();
        cp_wait<0>();
        __syncthreads();
    }

    unsigned qf[8][4];
#pragma unroll
    for (int kat = 0; kat < 8; kat++) {
        int kb = kat * 8;
        int r0 = warp * 16 + g4;
        qf[kat][0] = smu[(r0    ) * KVSH + kb + q4];
        qf[kat][1] = smu[(r0 + 8) * KVSH + kb + q4];
        qf[kat][2] = smu[(r0    ) * KVSH + kb + 4 + q4];
        qf[kat][3] = smu[(r0 + 8) * KVSH + kb + 4 + q4];
    }
    __syncthreads();

    const size_t kvrow = (size_t)HKV_ * DK_;
    const __half* Kb = g_Kh + (((size_t)b * T_ * HKV_ + hkv) * DK_);
    const __half* Vb = g_Vh + (((size_t)b * T_ * HKV_ + hkv) * DK_);

#define KV_ISSUE(stg, kt) do {                                                \
        int kb0 = (kt) * FBN;                                                 \
        unsigned sb = smem_base + (unsigned)((stg) * SKVH * 4);               \
        _Pragma("unroll")                                                     \
        for (int i = 0; i < 8; i++) {                                         \
            int c  = tid + 256 * i;                                           \
            int tn = c >> 10;                                                 \
            int r  = (c >> 4) & 63;                                           \
            int cc = c & 15;                                                  \
            const __half* src = (tn ? Vb : Kb) + (size_t)(kb0 + r) * kvrow + cc * 8; \
            cp16(sb + (unsigned)(((tn * 64 + r) * KVSH + cc * 4) * 4), src);  \
        }                                                                     \
    } while (0)

    float oacc[16][4];
#pragma unroll
    for (int i = 0; i < 16; i++)
#pragma unroll
        for (int j = 0; j < 4; j++) oacc[i][j] = 0.f;
    float m0 = -1e30f, m1 = -1e30f, l0 = 0.f, l1 = 0.f;
    const float sc = 0.08838834764831845f;

    const int nchunks = (qtile + 1) * (FBM / FBN);

    KV_ISSUE(0, 0); cp_commit();

    for (int kt = 0; kt < nchunks; kt++) {
        cp_wait<0>();
        __syncthreads();
        if (kt + 1 < nchunks) KV_ISSUE((kt + 1) & 1, kt + 1);
        cp_commit();

        const int kbase = kt * FBN;
        unsigned* Ks = smu + (kt & 1) * SKVH;
        const unsigned vbase = smem_base +
            (unsigned)(((kt & 1) * SKVH + 64 * KVSH) * 4);

        if (kbase <= wrmax) {
            float sacc[8][4];
#pragma unroll
            for (int n = 0; n < 8; n++)
#pragma unroll
                for (int j = 0; j < 4; j++) sacc[n][j] = 0.f;

#pragma unroll
            for (int kat = 0; kat < 8; kat++) {
                int kb = kat * 8;
#pragma unroll
                for (int nat = 0; nat < 8; nat++) {
                    unsigned bb[2];
                    bb[0] = Ks[(nat * 8 + g4) * KVSH + kb + q4];
                    bb[1] = Ks[(nat * 8 + g4) * KVSH + kb + 4 + q4];
                    mma_f16(sacc[nat], qf[kat], bb);
                }
            }

            const bool needmask = (kbase + FBN - 1 > rA);
#pragma unroll
            for (int nat = 0; nat < 8; nat++) {
                int c0 = kbase + nat * 8 + 2 * q4;
                sacc[nat][0] *= sc; sacc[nat][1] *= sc;
                sacc[nat][2] *= sc; sacc[nat][3] *= sc;
                if (needmask) {
                    if (c0     > rA) sacc[nat][0] = -1e30f;
                    if (c0 + 1 > rA) sacc[nat][1] = -1e30f;
                    if (c0     > rB) sacc[nat][2] = -1e30f;
                    if (c0 + 1 > rB) sacc[nat][3] = -1e30f;
                }
            }

            float mA = -1e30f, mB = -1e30f;
#pragma unroll
            for (int nat = 0; nat < 8; nat++) {
                mA = fmaxf(mA, fmaxf(sacc[nat][0], sacc[nat][1]));
                mB = fmaxf(mB, fmaxf(sacc[nat][2], sacc[nat][3]));
            }
            mA = fmaxf(mA, __shfl_xor_sync(0xffffffffu, mA, 1));
            mA = fmaxf(mA, __shfl_xor_sync(0xffffffffu, mA, 2));
            mB = fmaxf(mB, __shfl_xor_sync(0xffffffffu, mB, 1));
            mB = fmaxf(mB, __shfl_xor_sync(0xffffffffu, mB, 2));

            float nm0 = fmaxf(m0, mA), nm1 = fmaxf(m1, mB);
            float corr0 = __expf(m0 - nm0);
            float corr1 = __expf(m1 - nm1);
            float ps0 = 0.f, ps1 = 0.f;
#pragma unroll
            for (int nat = 0; nat < 8; nat++) {
                sacc[nat][0] = __expf(sacc[nat][0] - nm0);
                sacc[nat][1] = __expf(sacc[nat][1] - nm0);
                sacc[nat][2] = __expf(sacc[nat][2] - nm1);
                sacc[nat][3] = __expf(sacc[nat][3] - nm1);
                ps0 += sacc[nat][0] + sacc[nat][1];
                ps1 += sacc[nat][2] + sacc[nat][3];
            }
            ps0 += __shfl_xor_sync(0xffffffffu, ps0, 1);
            ps0 += __shfl_xor_sync(0xffffffffu, ps0, 2);
            ps1 += __shfl_xor_sync(0xffffffffu, ps1, 1);
            ps1 += __shfl_xor_sync(0xffffffffu, ps1, 2);
            l0 = l0 * corr0 + ps0;
            l1 = l1 * corr1 + ps1;
            m0 = nm0; m1 = nm1;

#pragma unroll
            for (int nv = 0; nv < 16; nv++) {
                oacc[nv][0] *= corr0; oacc[nv][1] *= corr0;
                oacc[nv][2] *= corr1; oacc[nv][3] *= corr1;
            }

#pragma unroll
            for (int nat = 0; nat < 8; nat++) {
                int wc = nat * 4 + q4;
                __half2 h0 = __floats2half2_rn(sacc[nat][0], sacc[nat][1]);
                __half2 h1 = __floats2half2_rn(sacc[nat][2], sacc[nat][3]);
                Ps[g4 * PSTH + wc]       = *(unsigned*)&h0;
                Ps[(g4 + 8) * PSTH + wc] = *(unsigned*)&h1;
            }
            __syncwarp();

#pragma unroll
            for (int kat = 0; kat < 4; kat++) {
                int kb = kat * 8;
                unsigned af[4];
                af[0] = Ps[(g4    ) * PSTH + kb + q4];
                af[1] = Ps[(g4 + 8) * PSTH + kb + q4];
                af[2] = Ps[(g4    ) * PSTH + kb + 4 + q4];
                af[3] = Ps[(g4 + 8) * PSTH + kb + 4 + q4];
                unsigned vrow = vbase +
                    (unsigned)(((kat * 16 + (lane & 15)) * KVSH) * 4);
#pragma unroll
                for (int nv = 0; nv < 16; nv++) {
                    unsigned bb[2];
                    asm volatile(
                        "ldmatrix.sync.aligned.m8n8.x2.trans.shared.b16 {%0,%1}, [%2];"
                        : "=r"(bb[0]), "=r"(bb[1])
                        : "r"(vrow + (unsigned)(nv * 16)));
                    mma_f16(oacc[nv], af, bb);
                }
            }
            __syncwarp();
        }
    }

    float inv0 = 1.f / l0, inv1 = 1.f / l1;
    __half* OA = g_Oh + (((size_t)(b * T_ + rA) * H_ + h) * DK_);
    __half* OB = g_Oh + (((size_t)(b * T_ + rB) * H_ + h) * DK_);
#pragma unroll
    for (int nv = 0; nv < 16; nv++) {
        int cc = nv * 8 + 2 * q4;
        *(__half2*)(OA + cc) = __floats2half2_rn(oacc[nv][0] * inv0, oacc[nv][1] * inv0);
        *(__half2*)(OB + cc) = __floats2half2_rn(oacc[nv][2] * inv1, oacc[nv][3] * inv1);
    }
#undef KV_ISSUE
}

// ---------------------------------------------------------------------------
// Launch
// ---------------------------------------------------------------------------
extern "C" void kernel_launch(void* const* d_in, const int* in_sizes, int n_in,
                              void* d_out, int out_size)
{
    const float* x       = (const float*)d_in[0];
    const float* wq      = (const float*)d_in[1];
    const float* wk      = (const float*)d_in[2];
    const float* wv      = (const float*)d_in[3];
    const float* wo      = (const float*)d_in[4];
    const float* q_normw = (const float*)d_in[5];
    const float* k_normw = (const float*)d_in[6];
    float* out = (float*)d_out;

    __half *Xh, *Wqkvh, *Woh, *Oh;
    cudaGetSymbolAddress((void**)&Xh, g_Xh);
    cudaGetSymbolAddress((void**)&Wqkvh, g_Wqkvh);
    cudaGetSymbolAddress((void**)&Woh, g_Woh);
    cudaGetSymbolAddress((void**)&Oh, g_Oh);

    const int M = B_ * T_;   // 4096

    // One fused conversion launch (x, wq, wk, wv, wo -> fp16 destinations)
    convert_all_kernel<<<(CN_TOTAL + 255) / 256, 256>>>(x, wq, wk, wv, wo);

    int gsmem = GSTG * GST_WORDS * 2 * (int)sizeof(unsigned);   // 61440 B
    cudaFuncSetAttribute(gemm_f16, cudaFuncAttributeMaxDynamicSharedMemorySize, gsmem);

    // Fused QKV projection
    gemm_f16<<<dim3(3072 / 128, M / 128), 256, gsmem>>>(
        Xh, Wqkvh, nullptr, M, 3072, DM_, 1);

    // RMSNorm + RoPE for Q and K in one launch (fp32 in, fp16 out)
    {
        int total_rows = B_ * T_ * (H_ + HKV_);   // 81920 warps
        rmsnorm_rope_all<<<total_rows / 4, 128>>>(q_normw, k_normw);
    }

    // FP16 flash attention
    {
        int smem = SMW_H * (int)sizeof(unsigned);   // 88064 B
        cudaFuncSetAttribute(flash_attn_f16, cudaFuncAttributeMaxDynamicSharedMemorySize, smem);
        flash_attn_f16<<<dim3(T_ / FBM, H_, B_), 256, smem>>>();
    }

    // Output projection (fp16 in, fp32 out)
    gemm_f16<<<dim3(DM_ / 128, M / 128), 256, gsmem>>>(
        Oh, Woh, out, M, DM_, DM_, 0);
}